// round 5
// baseline (speedup 1.0000x reference)
#include <cuda_runtime.h>
#include <cuda_bf16.h>

// LBP uniform (P=8, R=1) over (B,C,H,W)=(32,3,512,512) float32.
// R5: L1TEX still top unit (65.9%) because every input row was loaded+scaled
// 3x (as top/center/bottom by different warps). Now each warp computes a
// 2-row x 256-col strip with a rolling register buffer: 4 row-loads per 2
// output rows (2x amplification instead of 3x). Row-0 results stored before
// loading row h+2 (reusing the top buffer) to bound register pressure.

#define IMG_W 512
#define IMG_H 512

__device__ __forceinline__ float fset_ge(float a, float b) {
    float d;
    asm("set.ge.f32.f32 %0, %1, %2;" : "=f"(d) : "f"(a), "f"(b));
    return d;  // 1.0f if a>=b else 0.0f
}

// Load one row segment (8 px/lane), scale by 255, fill halos [0]/[9].
__device__ __forceinline__ void load_row(const float* p, bool valid,
                                         bool hasLeft, bool hasRight,
                                         int lane, int col, float q[10]) {
    const float4 z4 = make_float4(0.f, 0.f, 0.f, 0.f);
    float4 a = valid ? *reinterpret_cast<const float4*>(p + col)     : z4;
    float4 b = valid ? *reinterpret_cast<const float4*>(p + col + 4) : z4;
    q[1]=a.x*255.f; q[2]=a.y*255.f; q[3]=a.z*255.f; q[4]=a.w*255.f;
    q[5]=b.x*255.f; q[6]=b.y*255.f; q[7]=b.z*255.f; q[8]=b.w*255.f;
    q[0] = __shfl_up_sync(0xFFFFFFFFu, q[8], 1);
    q[9] = __shfl_down_sync(0xFFFFFFFFu, q[1], 1);
    if (lane == 0)  q[0] = (valid && hasLeft)  ? p[-1]  * 255.f : 0.f;
    if (lane == 31) q[9] = (valid && hasRight) ? p[256] * 255.f : 0.f;
}

__device__ __forceinline__ void compute_row(const float qt[10], const float qc[10],
                                            const float qb[10], float res[8]) {
#pragma unroll
    for (int j = 0; j < 8; j++) {
        const float ctr = floorf(qc[j + 1]);  // only centers need floor
        // circular order: tl, t, tr, r, br, b, bl, l  (bits 0..7)
        float m;
        m = fset_ge(qt[j    ], ctr);
        m = fmaf(fset_ge(qt[j + 1], ctr),   2.0f, m);
        m = fmaf(fset_ge(qt[j + 2], ctr),   4.0f, m);
        m = fmaf(fset_ge(qc[j + 2], ctr),   8.0f, m);
        m = fmaf(fset_ge(qb[j + 2], ctr),  16.0f, m);
        m = fmaf(fset_ge(qb[j + 1], ctr),  32.0f, m);
        m = fmaf(fset_ge(qb[j    ], ctr),  64.0f, m);
        m = fmaf(fset_ge(qc[j    ], ctr), 128.0f, m);
        const unsigned mi  = (unsigned)(int)m;
        const unsigned rot = ((mi << 1) | (mi >> 7)) & 0xFFu;
        const int trans = __popc(mi ^ rot);
        const int ones  = __popc(mi);
        res[j] = (float)((trans <= 2) ? ones : 9) * (1.0f / 255.0f);
    }
}

__global__ __launch_bounds__(256)
void lbp_kernel(const float* __restrict__ x, float* __restrict__ out, int npairs) {
    const int warpG = blockIdx.x * (blockDim.x >> 5) + (threadIdx.x >> 5);
    const int lane  = threadIdx.x & 31;
    const int pr = warpG >> 1;       // row-pair index over B*C*H/2
    const int s  = warpG & 1;        // 256-col segment
    if (pr >= npairs) return;

    const int r0 = pr * 2;           // first flattened row of the pair
    const int h0 = r0 & (IMG_H - 1); // even; pair never straddles images (H even)
    const bool hasTop = (h0 != 0);
    const bool hasBot = (h0 + 1 != IMG_H - 1);
    const bool hasLeft  = (s != 0);
    const bool hasRight = (s != 1);

    const float* p0 = x + (size_t)r0 * IMG_W + s * 256;  // row h0
    const int col = lane * 8;

    float qx[10], q0[10], q1[10];    // qx holds top first, then bottom
    load_row(p0 - IMG_W, hasTop, hasLeft, hasRight, lane, col, qx);
    load_row(p0,         true,   hasLeft, hasRight, lane, col, q0);
    load_row(p0 + IMG_W, true,   hasLeft, hasRight, lane, col, q1);

    float res[8];
    compute_row(qx, q0, q1, res);
    float* op = out + (size_t)r0 * IMG_W + s * 256 + col;
    *reinterpret_cast<float4*>(op)     = make_float4(res[0], res[1], res[2], res[3]);
    *reinterpret_cast<float4*>(op + 4) = make_float4(res[4], res[5], res[6], res[7]);

    // reuse qx for the bottom row (h0+2)
    load_row(p0 + 2 * IMG_W, hasBot, hasLeft, hasRight, lane, col, qx);
    compute_row(q0, q1, qx, res);
    op += IMG_W;
    *reinterpret_cast<float4*>(op)     = make_float4(res[0], res[1], res[2], res[3]);
    *reinterpret_cast<float4*>(op + 4) = make_float4(res[4], res[5], res[6], res[7]);
}

extern "C" void kernel_launch(void* const* d_in, const int* in_sizes, int n_in,
                              void* d_out, int out_size) {
    const float* x = (const float*)d_in[0];
    float* out = (float*)d_out;
    const int nrows  = out_size / IMG_W;   // B*C*H
    const int npairs = nrows / 2;          // H=512 even -> exact
    const int nwarps = npairs * 2;         // 2 segments of 256 cols
    const int threads = 256;               // 8 warps/block
    const int blocks = (nwarps + 7) / 8;
    lbp_kernel<<<blocks, threads>>>(x, out, npairs);
}